// round 14
// baseline (speedup 1.0000x reference)
#include <cuda_runtime.h>
#include <math.h>

// ---------------------------------------------------------------------------
// CReST loss, 4 launches (single stream):
//   1. k_rows   : fused wu rows (maxp + t_m) + x rows (supervised CE)
//   2. k_mid    : seghist+rank -> [gridsync] -> scan/thresholds -> [gridsync]
//                 -> compact (256 resident blocks, atomic-spin grid sync)
//   3. k_su     : unsupervised CE, small fixed grid striding over alist
//   4. k_reduce : deterministic final reduction (+ resets sync counters)
//   out[0]=loss, out[1]=Lx, out[2]=Lu, out[3..3+N)=max_probs
// ---------------------------------------------------------------------------

#define FULLMASK 0xffffffffu
#define MAXC 1024
#define SEG 256
#define MAXN 65536
#define NSEG_MAX (MAXN / SEG)
#define MAXBX 32768
#define WPB 8
#define L2E 1.4426950408889634f
#define SU_BLOCKS 128                    // k_su fixed grid

__device__ int           g_tm[MAXN];
__device__ unsigned char g_local[MAXN];
__device__ float         g_ce_x[MAXBX];
__device__ float         g_ce_u[MAXN];
__device__ int           g_seg_counts_t[MAXC][NSEG_MAX];  // [class][segment]
__device__ int           g_thr[NSEG_MAX][MAXC];           // bn[c]-seg_off[s][c]
__device__ int           g_alist[MAXN];
__device__ unsigned int  g_nact = 0;      // reset in k_mid phase A
__device__ unsigned int  g_ph1 = 0;       // grid-sync counters,
__device__ unsigned int  g_ph2 = 0;       // reset by k_reduce

// ---- 1: fused wu (maxp + t_m) and x (supervised CE) rows --------------------
__global__ void __launch_bounds__(WPB * 32, 8)
k_rows(const float* __restrict__ lwu,
       const float* __restrict__ lx,
       const int* __restrict__ tgts,
       int C, int N, int Bx,
       float* __restrict__ maxp_out) {
    int lane = threadIdx.x & 31;
    int gw = blockIdx.x * WPB + (threadIdx.x >> 5);
    int n4 = C >> 2;
    int tail = C & 3;

    if (gw < N) {
        // ---- weak-aug row: sum-of-exp + inline first-index argmax ----
        const float* rowp = lwu + (size_t)gw * C;
        const float4* rp = (const float4*)rowp;

        float m = -INFINITY;
        int bi = 0x3fffffff;
        float s0 = 0.f, s1 = 0.f;
        #pragma unroll
        for (int u = 0; u < 8; u++) {
            int k = lane + u * 32;
            if (k < n4) {
                float4 c = __ldcs(rp + k);
                int j = 4 * k;
                if (c.x > m) { m = c.x; bi = j; }
                if (c.y > m) { m = c.y; bi = j + 1; }
                if (c.z > m) { m = c.z; bi = j + 2; }
                if (c.w > m) { m = c.w; bi = j + 3; }
                s0 += exp2f(c.x * L2E) + exp2f(c.y * L2E);
                s1 += exp2f(c.z * L2E) + exp2f(c.w * L2E);
            }
        }
        if (tail && lane < tail) {
            int j = 4 * n4 + lane;
            float tv = __ldcs(rowp + j);
            if (tv > m) { m = tv; bi = j; }
            s0 += exp2f(tv * L2E);
        }
        float s = s0 + s1;

        #pragma unroll
        for (int o = 16; o; o >>= 1) {
            float om = __shfl_xor_sync(FULLMASK, m, o);
            int   oi = __shfl_xor_sync(FULLMASK, bi, o);
            s += __shfl_xor_sync(FULLMASK, s, o);
            if (om > m || (om == m && oi < bi)) { m = om; bi = oi; }
        }

        if (lane == 0) {
            float maxp = exp2f(m * L2E) / s;
            maxp_out[gw] = maxp;
            g_tm[gw] = (maxp >= 0.95f) ? bi : 0;
        }
    } else if (gw < N + Bx) {
        // ---- supervised row: sum-of-exp; target via broadcast load ----
        int row = gw - N;
        const float* rowp = lx + (size_t)row * C;
        const float4* rp = (const float4*)rowp;
        float tval = __ldg(rowp + tgts[row]);

        float s0 = 0.f, s1 = 0.f;
        #pragma unroll
        for (int u = 0; u < 8; u++) {
            int k = lane + u * 32;
            if (k < n4) {
                float4 c = __ldcs(rp + k);
                s0 += exp2f(c.x * L2E) + exp2f(c.y * L2E);
                s1 += exp2f(c.z * L2E) + exp2f(c.w * L2E);
            }
        }
        if (tail && lane < tail)
            s0 += exp2f(__ldcs(rowp + 4 * n4 + lane) * L2E);
        float s = s0 + s1;

        #pragma unroll
        for (int o = 16; o; o >>= 1) s += __shfl_xor_sync(FULLMASK, s, o);

        if (lane == 0)
            g_ce_x[row] = logf(s) - tval;
    }
}

// ---- grid sync for a fully-resident grid ------------------------------------
__device__ __forceinline__ void grid_sync(volatile unsigned int* ctr, int nblk) {
    __syncthreads();
    __threadfence();                         // release this block's writes
    if (threadIdx.x == 0) {
        atomicAdd((unsigned int*)ctr, 1u);
        while (*ctr < (unsigned)nblk) { }    // volatile L2 poll
        __threadfence();                     // acquire other blocks' writes
    }
    __syncthreads();
}

// ---- 2: fused seghist+rank -> scan/thresholds -> compact --------------------
// grid = nseg (256) blocks, 256 threads; all blocks resident (smem 8KB).
__global__ void __launch_bounds__(SEG, 2)
k_mid(int N, int C, int nseg, const float* __restrict__ gtp) {
    __shared__ unsigned char whist[WPB][MAXC];
    int r = threadIdx.x;
    int w = r >> 5;
    int lane = r & 31;
    int b = blockIdx.x;
    int row = b * SEG + r;

    // ---- phase A: per-segment histogram + within-segment stable rank ----
    if (b == 0 && r == 0) g_nact = 0;   // prior k_su already consumed it

    unsigned int* hz = (unsigned int*)whist;
    #pragma unroll
    for (int i = r; i < WPB * MAXC / 4; i += SEG) hz[i] = 0u;

    int myc = (row < N) ? g_tm[row] : -1;

    unsigned int mmask = __match_any_sync(FULLMASK, myc);
    int within = __popc(mmask & ((1u << lane) - 1u));
    int leader = __ffs(mmask) - 1;

    __syncthreads();
    if (lane == leader && myc >= 0)
        whist[w][myc] = (unsigned char)__popc(mmask);
    __syncthreads();

    if (row < N) {
        int cross = 0;
        #pragma unroll
        for (int j = 0; j < WPB; j++)
            if (j < w) cross += whist[j][myc];
        g_local[row] = (unsigned char)(cross + within);
    }

    for (int c = r; c < C; c += SEG) {
        int cnt = 0;
        #pragma unroll
        for (int j = 0; j < WPB; j++) cnt += whist[j][c];
        g_seg_counts_t[c][b] = cnt;
    }

    grid_sync(&g_ph1, nseg);

    // ---- phase B: warp-per-class scan over segments, write thresholds ----
    {
        int c = b * WPB + w;
        if (c < C) {
            int P = (nseg + 31) / 32;            // segments per lane (<=8)
            int base = lane * P;
            int v[8];
            int sum = 0;
            #pragma unroll 8
            for (int i = 0; i < P; i++) {
                int sidx = base + i;
                v[i] = (sidx < nseg) ? g_seg_counts_t[c][sidx] : 0;
                sum += v[i];
            }
            int x = sum;
            #pragma unroll
            for (int o = 1; o < 32; o <<= 1) {
                int t = __shfl_up_sync(FULLMASK, x, o);
                if (lane >= o) x += t;
            }
            int tot = __shfl_sync(FULLMASK, x, 31);
            int run = x - sum;                   // exclusive offset
            // bn = round-half-even(total * gtp[c]), matching jnp.round
            int bn = (int)rintf((float)tot * __ldg(gtp + c));
            #pragma unroll 8
            for (int i = 0; i < P; i++) {
                int sidx = base + i;
                if (sidx < nseg) {
                    g_thr[sidx][c] = bn - run;
                    run += v[i];
                }
            }
        }
    }

    grid_sync(&g_ph2, nseg);

    // ---- phase C: compact active rows ----
    if (row < N) {
        int tgt = myc;
        bool active = false;
        if (tgt != 0)
            active = ((int)g_local[row] < g_thr[b][tgt]);
        if (active) {
            unsigned int p = atomicAdd(&g_nact, 1u);
            g_alist[p] = row;
        } else {
            g_ce_u[row] = 0.f;
        }
    }
}

// ---- 3: unsupervised CE; small fixed grid strides over active list ----------
__global__ void __launch_bounds__(WPB * 32, 8)
k_su(const float* __restrict__ lsu, int C) {
    int lane = threadIdx.x & 31;
    int nact = (int)g_nact;              // broadcast load
    int n4 = C >> 2;
    int tail = C & 3;
    const int stride = SU_BLOCKS * WPB;

    for (int w = blockIdx.x * WPB + (threadIdx.x >> 5); w < nact; w += stride) {
        int row = g_alist[w];
        int tgt = g_tm[row];

        const float* rowp = lsu + (size_t)row * C;
        const float4* rp = (const float4*)rowp;
        float tval = __ldg(rowp + tgt);

        float s0 = 0.f, s1 = 0.f;
        #pragma unroll
        for (int u = 0; u < 8; u++) {
            int k = lane + u * 32;
            if (k < n4) {
                float4 c = __ldcs(rp + k);
                s0 += exp2f(c.x * L2E) + exp2f(c.y * L2E);
                s1 += exp2f(c.z * L2E) + exp2f(c.w * L2E);
            }
        }
        if (tail && lane < tail)
            s0 += exp2f(__ldcs(rowp + 4 * n4 + lane) * L2E);
        float s = s0 + s1;

        #pragma unroll
        for (int o = 16; o; o >>= 1) s += __shfl_xor_sync(FULLMASK, s, o);

        if (lane == 0)
            g_ce_u[row] = logf(s) - tval;
    }
}

// ---- 4: deterministic final reduction (+ counter reset for next replay) -----
__global__ void k_reduce(int Bx, int N, float* __restrict__ out) {
    __shared__ float sh[1024];
    __shared__ float lx_s;
    int tid = threadIdx.x;

    if (tid == 0) { g_ph1 = 0; g_ph2 = 0; }   // reset grid-sync counters

    float a = 0.f;
    for (int i = tid; i < Bx; i += 1024) a += g_ce_x[i];
    sh[tid] = a;
    __syncthreads();
    for (int o = 512; o; o >>= 1) {
        if (tid < o) sh[tid] += sh[tid + o];
        __syncthreads();
    }
    if (tid == 0) lx_s = sh[0];
    __syncthreads();

    float b = 0.f;
    for (int i = tid; i < N; i += 1024) b += g_ce_u[i];
    sh[tid] = b;
    __syncthreads();
    for (int o = 512; o; o >>= 1) {
        if (tid < o) sh[tid] += sh[tid + o];
        __syncthreads();
    }
    if (tid == 0) {
        float Lx = lx_s / (float)Bx;
        float Lu = sh[0] / (float)N;
        out[0] = Lx + Lu;  // LAMBDA_U = 1.0
        out[1] = Lx;
        out[2] = Lu;
    }
}

// ---------------------------------------------------------------------------
extern "C" void kernel_launch(void* const* d_in, const int* in_sizes, int n_in,
                              void* d_out, int out_size) {
    const float* lx  = (const float*)d_in[0];
    const float* lwu = (const float*)d_in[1];
    const float* lsu = (const float*)d_in[2];
    const int*   tx  = (const int*)d_in[3];
    const float* gtp = (const float*)d_in[4];
    // d_in[5] = t (unused)

    int Bx = in_sizes[3];
    int C  = in_sizes[4];
    int N  = in_sizes[1] / C;
    int nseg = (N + SEG - 1) / SEG;

    float* out = (float*)d_out;

    int rows = N + Bx;
    int blk_rows = (rows + WPB - 1) / WPB;

    k_rows<<<blk_rows, WPB * 32>>>(lwu, lx, tx, C, N, Bx, out + 3);  // 1
    k_mid<<<nseg, SEG>>>(N, C, nseg, gtp);                           // 2
    k_su<<<SU_BLOCKS, WPB * 32>>>(lsu, C);                           // 3
    k_reduce<<<1, 1024>>>(Bx, N, out);                               // 4 <- profiled
}

// round 15
// speedup vs baseline: 1.0754x; 1.0754x over previous
#include <cuda_runtime.h>
#include <math.h>

// ---------------------------------------------------------------------------
// CReST loss, 7 launches (R11 structure + split parallel reduction):
//   1. k_rows    : fused wu rows (maxp + t_m) + x rows (supervised CE)
//   2. k_seghist_rank : per-segment class counts (transposed) + stable rank
//   3. k_scan    : per-class scan over segments -> thresholds (bn - off)
//   4. k_compact : build active-row list (single gather)
//   5. k_su      : unsupervised CE for active rows (early-exit warps)
//   6. k_reduce1 : 64-block partial sums (deterministic slices)
//   7. k_reduce2 : final fixed-order sum of partials
//   out[0]=loss, out[1]=Lx, out[2]=Lu, out[3..3+N)=max_probs
// ---------------------------------------------------------------------------

#define FULLMASK 0xffffffffu
#define MAXC 1024
#define SEG 256
#define MAXN 65536
#define NSEG_MAX (MAXN / SEG)
#define MAXBX 32768
#define WPB 8
#define L2E 1.4426950408889634f
#define RED_BLOCKS 64

__device__ int           g_tm[MAXN];
__device__ unsigned char g_local[MAXN];
__device__ float         g_ce_x[MAXBX];
__device__ float         g_ce_u[MAXN];
__device__ int           g_seg_counts_t[MAXC][NSEG_MAX];  // [class][segment]
__device__ int           g_thr[NSEG_MAX][MAXC];           // bn[c]-seg_off[s][c]
__device__ int           g_alist[MAXN];
__device__ unsigned int  g_nact = 0;             // reset by k_scan
__device__ float         g_part_x[RED_BLOCKS];
__device__ float         g_part_u[RED_BLOCKS];

// ---- 1: fused wu (maxp + t_m) and x (supervised CE) rows --------------------
__global__ void __launch_bounds__(WPB * 32, 8)
k_rows(const float* __restrict__ lwu,
       const float* __restrict__ lx,
       const int* __restrict__ tgts,
       int C, int N, int Bx,
       float* __restrict__ maxp_out) {
    int lane = threadIdx.x & 31;
    int gw = blockIdx.x * WPB + (threadIdx.x >> 5);
    int n4 = C >> 2;
    int tail = C & 3;

    if (gw < N) {
        // ---- weak-aug row: sum-of-exp + inline first-index argmax ----
        const float* rowp = lwu + (size_t)gw * C;
        const float4* rp = (const float4*)rowp;

        float m = -INFINITY;
        int bi = 0x3fffffff;
        float s0 = 0.f, s1 = 0.f;
        #pragma unroll
        for (int u = 0; u < 8; u++) {
            int k = lane + u * 32;
            if (k < n4) {
                float4 c = __ldcs(rp + k);
                int j = 4 * k;
                if (c.x > m) { m = c.x; bi = j; }
                if (c.y > m) { m = c.y; bi = j + 1; }
                if (c.z > m) { m = c.z; bi = j + 2; }
                if (c.w > m) { m = c.w; bi = j + 3; }
                s0 += exp2f(c.x * L2E) + exp2f(c.y * L2E);
                s1 += exp2f(c.z * L2E) + exp2f(c.w * L2E);
            }
        }
        if (tail && lane < tail) {
            int j = 4 * n4 + lane;
            float tv = __ldcs(rowp + j);
            if (tv > m) { m = tv; bi = j; }
            s0 += exp2f(tv * L2E);
        }
        float s = s0 + s1;

        #pragma unroll
        for (int o = 16; o; o >>= 1) {
            float om = __shfl_xor_sync(FULLMASK, m, o);
            int   oi = __shfl_xor_sync(FULLMASK, bi, o);
            s += __shfl_xor_sync(FULLMASK, s, o);
            if (om > m || (om == m && oi < bi)) { m = om; bi = oi; }
        }

        if (lane == 0) {
            float maxp = exp2f(m * L2E) / s;
            maxp_out[gw] = maxp;
            g_tm[gw] = (maxp >= 0.95f) ? bi : 0;
        }
    } else if (gw < N + Bx) {
        // ---- supervised row: sum-of-exp; target via broadcast load ----
        int row = gw - N;
        const float* rowp = lx + (size_t)row * C;
        const float4* rp = (const float4*)rowp;
        float tval = __ldg(rowp + tgts[row]);

        float s0 = 0.f, s1 = 0.f;
        #pragma unroll
        for (int u = 0; u < 8; u++) {
            int k = lane + u * 32;
            if (k < n4) {
                float4 c = __ldcs(rp + k);
                s0 += exp2f(c.x * L2E) + exp2f(c.y * L2E);
                s1 += exp2f(c.z * L2E) + exp2f(c.w * L2E);
            }
        }
        if (tail && lane < tail)
            s0 += exp2f(__ldcs(rowp + 4 * n4 + lane) * L2E);
        float s = s0 + s1;

        #pragma unroll
        for (int o = 16; o; o >>= 1) s += __shfl_xor_sync(FULLMASK, s, o);

        if (lane == 0)
            g_ce_x[row] = logf(s) - tval;
    }
}

// ---- 2: per-segment class counts (transposed) + within-segment stable rank --
__global__ void k_seghist_rank(int N, int C) {
    __shared__ unsigned char whist[WPB][MAXC];
    int r = threadIdx.x;
    int w = r >> 5;
    int lane = r & 31;
    int row = blockIdx.x * SEG + r;

    unsigned int* hz = (unsigned int*)whist;
    #pragma unroll
    for (int i = r; i < WPB * MAXC / 4; i += SEG) hz[i] = 0u;

    int myc = (row < N) ? g_tm[row] : -1;

    unsigned int mmask = __match_any_sync(FULLMASK, myc);
    int within = __popc(mmask & ((1u << lane) - 1u));
    int leader = __ffs(mmask) - 1;

    __syncthreads();
    if (lane == leader && myc >= 0)
        whist[w][myc] = (unsigned char)__popc(mmask);
    __syncthreads();

    if (row < N) {
        int cross = 0;
        #pragma unroll
        for (int j = 0; j < WPB; j++)
            if (j < w) cross += whist[j][myc];
        g_local[row] = (unsigned char)(cross + within);
    }

    // transposed store: scattered writes, coalesced scan reads
    for (int c = r; c < C; c += SEG) {
        int cnt = 0;
        #pragma unroll
        for (int j = 0; j < WPB; j++) cnt += whist[j][c];
        g_seg_counts_t[c][blockIdx.x] = cnt;
    }
}

// ---- 3: per-class scan over segments -> thresholds --------------------------
__global__ void k_scan(int nseg, const float* __restrict__ gtp) {
    int c = blockIdx.x;
    int s = threadIdx.x;
    int lane = s & 31, w = s >> 5;

    if (c == 0 && s == 0) g_nact = 0;    // reset before k_compact fills it

    int v = (s < nseg) ? g_seg_counts_t[c][s] : 0;   // coalesced

    int x = v;
    #pragma unroll
    for (int o = 1; o < 32; o <<= 1) {
        int t = __shfl_up_sync(FULLMASK, x, o);
        if (lane >= o) x += t;
    }

    __shared__ int wsum[8];
    __shared__ int woff[8];
    __shared__ int tot;
    if (lane == 31) wsum[w] = x;
    __syncthreads();
    if (w == 0) {
        int y = (lane < 8) ? wsum[lane] : 0;
        #pragma unroll
        for (int o = 1; o < 8; o <<= 1) {
            int t = __shfl_up_sync(FULLMASK, y, o);
            if (lane >= o) y += t;
        }
        if (lane < 8) woff[lane] = y;
    }
    __syncthreads();

    int incl = x + (w ? woff[w - 1] : 0);
    if (s == SEG - 1) tot = incl;         // total count of class c
    __syncthreads();

    if (s < nseg) {
        // bn = round-half-even(total * gtp[c]), matching jnp.round
        int bn = (int)rintf((float)tot * gtp[c]);
        g_thr[s][c] = bn - (incl - v);    // bn - exclusive_offset
    }
}

// ---- 4: build active-row list (single gather) -------------------------------
__global__ void k_compact(int N) {
    int row = blockIdx.x * SEG + threadIdx.x;
    if (row >= N) return;
    int tgt = g_tm[row];
    bool active = false;
    if (tgt != 0)
        active = ((int)g_local[row] < g_thr[row >> 8][tgt]);
    if (active) {
        unsigned int p = atomicAdd(&g_nact, 1u);
        g_alist[p] = row;
    } else {
        g_ce_u[row] = 0.f;
    }
}

// ---- 5: unsupervised CE for active rows only --------------------------------
__global__ void __launch_bounds__(WPB * 32, 8)
k_su(const float* __restrict__ lsu, int C) {
    int lane = threadIdx.x & 31;
    int w = blockIdx.x * WPB + (threadIdx.x >> 5);
    if (w >= (int)g_nact) return;        // one broadcast load, then exit
    int row = g_alist[w];
    int tgt = g_tm[row];

    const float* rowp = lsu + (size_t)row * C;
    const float4* rp = (const float4*)rowp;
    int n4 = C >> 2;
    int tail = C & 3;
    float tval = __ldg(rowp + tgt);

    float s0 = 0.f, s1 = 0.f;
    #pragma unroll
    for (int u = 0; u < 8; u++) {
        int k = lane + u * 32;
        if (k < n4) {
            float4 c = __ldcs(rp + k);
            s0 += exp2f(c.x * L2E) + exp2f(c.y * L2E);
            s1 += exp2f(c.z * L2E) + exp2f(c.w * L2E);
        }
    }
    if (tail && lane < tail)
        s0 += exp2f(__ldcs(rowp + 4 * n4 + lane) * L2E);
    float s = s0 + s1;

    #pragma unroll
    for (int o = 16; o; o >>= 1) s += __shfl_xor_sync(FULLMASK, s, o);

    if (lane == 0)
        g_ce_u[row] = logf(s) - tval;
}

// ---- 6: 64-block partial sums (deterministic contiguous slices) -------------
__global__ void k_reduce1(int Bx, int N) {
    __shared__ float sh[256];
    int b = blockIdx.x;
    int tid = threadIdx.x;

    // slice of g_ce_x
    int per_x = (Bx + RED_BLOCKS - 1) / RED_BLOCKS;
    int x0 = b * per_x, x1 = min(x0 + per_x, Bx);
    float a = 0.f;
    for (int i = x0 + tid; i < x1; i += 256) a += g_ce_x[i];
    sh[tid] = a;
    __syncthreads();
    for (int o = 128; o; o >>= 1) {
        if (tid < o) sh[tid] += sh[tid + o];
        __syncthreads();
    }
    if (tid == 0) g_part_x[b] = sh[0];
    __syncthreads();

    // slice of g_ce_u
    int per_u = (N + RED_BLOCKS - 1) / RED_BLOCKS;
    int u0 = b * per_u, u1 = min(u0 + per_u, N);
    float c = 0.f;
    for (int i = u0 + tid; i < u1; i += 256) c += g_ce_u[i];
    sh[tid] = c;
    __syncthreads();
    for (int o = 128; o; o >>= 1) {
        if (tid < o) sh[tid] += sh[tid + o];
        __syncthreads();
    }
    if (tid == 0) g_part_u[b] = sh[0];
}

// ---- 7: final fixed-order sum of partials -----------------------------------
__global__ void k_reduce2(int Bx, int N, float* __restrict__ out) {
    if (threadIdx.x == 0) {
        float sx = 0.f, su = 0.f;
        #pragma unroll
        for (int i = 0; i < RED_BLOCKS; i++) { sx += g_part_x[i]; su += g_part_u[i]; }
        float Lx = sx / (float)Bx;
        float Lu = su / (float)N;
        out[0] = Lx + Lu;  // LAMBDA_U = 1.0
        out[1] = Lx;
        out[2] = Lu;
    }
}

// ---------------------------------------------------------------------------
extern "C" void kernel_launch(void* const* d_in, const int* in_sizes, int n_in,
                              void* d_out, int out_size) {
    const float* lx  = (const float*)d_in[0];
    const float* lwu = (const float*)d_in[1];
    const float* lsu = (const float*)d_in[2];
    const int*   tx  = (const int*)d_in[3];
    const float* gtp = (const float*)d_in[4];
    // d_in[5] = t (unused)

    int Bx = in_sizes[3];
    int C  = in_sizes[4];
    int N  = in_sizes[1] / C;
    int nseg = (N + SEG - 1) / SEG;

    float* out = (float*)d_out;

    int rows = N + Bx;
    int blk_rows = (rows + WPB - 1) / WPB;
    int blk_n    = (N + WPB - 1) / WPB;

    k_rows<<<blk_rows, WPB * 32>>>(lwu, lx, tx, C, N, Bx, out + 3);  // 1
    k_seghist_rank<<<nseg, SEG>>>(N, C);                             // 2
    k_scan<<<C, SEG>>>(nseg, gtp);                                   // 3
    k_compact<<<nseg, SEG>>>(N);                                     // 4 <- profiled
    k_su<<<blk_n, WPB * 32>>>(lsu, C);                               // 5
    k_reduce1<<<RED_BLOCKS, 256>>>(Bx, N);                           // 6
    k_reduce2<<<1, 32>>>(Bx, N, out);                                // 7
}